// round 16
// baseline (speedup 1.0000x reference)
#include <cuda_runtime.h>
#include <cuda_bf16.h>
#include <cuda_fp16.h>
#include <cstdint>
#include <cstddef>

// Problem constants
#define NB    8
#define NCH   256
#define NTOK  4096
#define CHB   ((size_t)NCH * NTOK)

typedef __nv_bfloat16 bf16;

// Static scratch — accessed ONLY via cudaGetSymbolAddress-resolved pointers.
__device__ __align__(256) float  g_stat[NB * 32 * 2];  // groupnorm mean/rstd
__device__ __align__(256) bf16   g_hnT[NB * CHB];   // [tok][ch] bf16
__device__ __align__(256) __half g_qT [NB * CHB];   // [tok][ch] fp16
__device__ __align__(256) __half g_kT [NB * CHB];   // [tok][ch] fp16
__device__ __align__(256) __half g_v  [NB * CHB];   // [ch][tok] fp16
__device__ __align__(256) bf16   g_aoT[NB * CHB];   // [tok][ch] bf16
__device__ __align__(256) bf16   g_wb [4 * NCH * NCH]; // bf16 weights q,k,v,o

// ---------------------------------------------------------------------------
// common PTX helpers
// ---------------------------------------------------------------------------
__device__ __forceinline__ void mma16816(float* c, unsigned a0, unsigned a1,
                                         unsigned a2, unsigned a3,
                                         unsigned b0, unsigned b1)
{
    asm volatile(
        "mma.sync.aligned.m16n8k16.row.col.f32.bf16.bf16.f32 "
        "{%0,%1,%2,%3},{%4,%5,%6,%7},{%8,%9},{%0,%1,%2,%3};"
        : "+f"(c[0]), "+f"(c[1]), "+f"(c[2]), "+f"(c[3])
        : "r"(a0), "r"(a1), "r"(a2), "r"(a3), "r"(b0), "r"(b1));
}

// fp16 operands, fp32 accumulate (PV + l)
__device__ __forceinline__ void mma16816h(float* c, unsigned a0, unsigned a1,
                                          unsigned a2, unsigned a3,
                                          unsigned b0, unsigned b1)
{
    asm volatile(
        "mma.sync.aligned.m16n8k16.row.col.f32.f16.f16.f32 "
        "{%0,%1,%2,%3},{%4,%5,%6,%7},{%8,%9},{%0,%1,%2,%3};"
        : "+f"(c[0]), "+f"(c[1]), "+f"(c[2]), "+f"(c[3])
        : "r"(a0), "r"(a1), "r"(a2), "r"(a3), "r"(b0), "r"(b1));
}

// fp16 operands, fp16 accumulate (S logits)
__device__ __forceinline__ void mma16816hh(unsigned* c, unsigned a0, unsigned a1,
                                           unsigned a2, unsigned a3,
                                           unsigned b0, unsigned b1)
{
    asm volatile(
        "mma.sync.aligned.m16n8k16.row.col.f16.f16.f16.f16 "
        "{%0,%1},{%2,%3,%4,%5},{%6,%7},{%0,%1};"
        : "+r"(c[0]), "+r"(c[1])
        : "r"(a0), "r"(a1), "r"(a2), "r"(a3), "r"(b0), "r"(b1));
}

#define LDSM4(r0, r1, r2, r3, addr) \
    asm volatile("ldmatrix.sync.aligned.m8n8.x4.shared.b16 {%0,%1,%2,%3}, [%4];" \
                 : "=r"(r0), "=r"(r1), "=r"(r2), "=r"(r3) : "r"(addr))

#define CP16(dst, src) \
    asm volatile("cp.async.cg.shared.global [%0], [%1], 16;" :: "r"(dst), "l"(src))
#define CPCOMMIT() asm volatile("cp.async.commit_group;" ::: "memory")
#define CPWAIT1()  asm volatile("cp.async.wait_group 1;" ::: "memory")
#define CPWAIT0()  asm volatile("cp.async.wait_group 0;" ::: "memory")
#define STS32(addr, v) \
    asm volatile("st.shared.u32 [%0], %1;" :: "r"(addr), "r"(v) : "memory")

__device__ __forceinline__ unsigned pkbf(float x, float y) {
    __nv_bfloat162 h = __floats2bfloat162_rn(x, y);
    return *(unsigned*)&h;
}
__device__ __forceinline__ unsigned pkh(float x, float y) {
    __half2 h = __floats2half2_rn(x, y);
    return *(unsigned*)&h;
}

// ---------------------------------------------------------------------------
// prep: weights fp32 -> bf16
// ---------------------------------------------------------------------------
__global__ __launch_bounds__(256) void prep_kernel(
    const float* __restrict__ wq, const float* __restrict__ wk,
    const float* __restrict__ wv, const float* __restrict__ wo,
    bf16* __restrict__ wb)
{
    int i = blockIdx.x * 256 + threadIdx.x;  // 65536
    wb[i]          = __float2bfloat16(wq[i]);
    wb[ 65536 + i] = __float2bfloat16(wk[i]);
    wb[131072 + i] = __float2bfloat16(wv[i]);
    wb[196608 + i] = __float2bfloat16(wo[i]);
}

// ---------------------------------------------------------------------------
// GroupNorm stats only: one block per (batch, group) -> mean, rstd
// ---------------------------------------------------------------------------
__global__ __launch_bounds__(256) void gn_stats_kernel(
    const float* __restrict__ x, float* __restrict__ stat)
{
    int bg = blockIdx.x;           // b*32 + g
    size_t base = (size_t)bg * 8 * NTOK;
    const float4* px = (const float4*)(x + base);
    int t = threadIdx.x;

    float s = 0.f, ss = 0.f;
#pragma unroll
    for (int r = 0; r < 32; r++) {
        float4 f = px[r * 256 + t];
        s  += f.x + f.y + f.z + f.w;
        ss += f.x * f.x + f.y * f.y + f.z * f.z + f.w * f.w;
    }
#pragma unroll
    for (int o = 16; o; o >>= 1) {
        s  += __shfl_xor_sync(0xffffffffu, s, o);
        ss += __shfl_xor_sync(0xffffffffu, ss, o);
    }
    __shared__ float rs[8], rss[8];
    if ((t & 31) == 0) { rs[t >> 5] = s; rss[t >> 5] = ss; }
    __syncthreads();
    if (t == 0) {
        float S = 0.f, SS = 0.f;
#pragma unroll
        for (int i = 0; i < 8; i++) { S += rs[i]; SS += rss[i]; }
        float m = S * (1.f / 32768.f);
        float var = SS * (1.f / 32768.f) - m * m;
        stat[bg * 2]     = m;
        stat[bg * 2 + 1] = rsqrtf(var + 1e-6f);
    }
}

// ---------------------------------------------------------------------------
// Transpose + normalize: x [256][4096] fp32 -> hnT [4096][256] bf16
// ---------------------------------------------------------------------------
__global__ __launch_bounds__(256) void transpose_norm_kernel(
    const float* __restrict__ x, const float* __restrict__ stat,
    const float* __restrict__ sc, const float* __restrict__ bi,
    bf16* __restrict__ out)
{
    __shared__ float tile[32][33];
    size_t z = blockIdx.z;
    const float* ip = x + z * CHB;
    bf16* op = out + z * CHB;
    int n0 = blockIdx.x * 32, c0 = blockIdx.y * 32;
    int tx = threadIdx.x & 31, ty = threadIdx.x >> 5;
#pragma unroll
    for (int j = 0; j < 32; j += 8) {
        int c = c0 + ty + j;
        float mean = stat[(z * 32 + (c >> 3)) * 2];
        float rstd = stat[(z * 32 + (c >> 3)) * 2 + 1];
        float a = sc[c] * rstd;
        float bb = bi[c] - mean * a;
        tile[ty + j][tx] = ip[(size_t)c * NTOK + n0 + tx] * a + bb;
    }
    __syncthreads();
#pragma unroll
    for (int j = 0; j < 32; j += 8)
        op[(size_t)(n0 + ty + j) * NCH + c0 + tx] = __float2bfloat16(tile[tx][ty + j]);
}

// ---------------------------------------------------------------------------
// hgemm: warp-MMA bf16 GEMM, 3-stage cp.async pipeline (round-9 proven).
// OUT_MODE: 0 fp32, 1 bf16, 2 fp16.
// ---------------------------------------------------------------------------
#define ASTRB 40
#define OPB   (128 * ASTRB * 2)
#define BUFB  (2 * OPB)
#define SMEM_DYN (3 * BUFB)

template<int OUT_MODE, int BIAS_MODE, int RESID>
__global__ __launch_bounds__(256, 2) void hgemm(
    const bf16* __restrict__ A, const bf16* __restrict__ B,
    void* __restrict__ Cout, const float* __restrict__ bias,
    const float* __restrict__ resid, float alpha, float outscale,
    int M, int N, int K, size_t bA, size_t bB, size_t bC)
{
    extern __shared__ char dynsm[];
    uint32_t sBase = (uint32_t)__cvta_generic_to_shared(dynsm);

    int t = threadIdx.x;
    int m0 = blockIdx.y * 128, n0 = blockIdx.x * 128;
    size_t z = blockIdx.z;

    int wid = t >> 5, lane = t & 31;
    int mw = (wid & 1) * 64, nw = (wid >> 1) * 32;
    int lr = lane >> 2, lc = lane & 3;

    float acc[64];
#pragma unroll
    for (int i = 0; i < 64; i++) acc[i] = 0.f;

    int rowa = t >> 2, gcol = t & 3;
    const bf16* Ab = A + z * bA + (size_t)(m0 + rowa) * K + gcol * 8;
    const bf16* Bb = B + z * bB + (size_t)(n0 + rowa) * K + gcol * 8;
    size_t rstep = (size_t)64 * K;

    uint32_t stOff   = (uint32_t)(rowa * ASTRB + gcol * 8) * 2;
    uint32_t stOff64 = stOff + (uint32_t)(64 * ASTRB) * 2;

    int arow_l = (lane & 7) + ((lane >> 3) & 1) * 8;
    int akof_l = (lane >> 4) * 8;
    int brow_l = (lane & 7) + ((lane >> 4) & 1) * 8;
    int bkof_l = ((lane >> 3) & 1) * 8;

    int nkt = K / 32;

#define STAGE(chunk, buf) do {                                        \
        size_t go = (size_t)(chunk) * 32;                             \
        uint32_t ab = sBase + (uint32_t)(buf) * BUFB;                 \
        uint32_t bb2 = ab + OPB;                                      \
        CP16(ab + stOff,    Ab + go);                                 \
        CP16(ab + stOff64,  Ab + go + rstep);                         \
        CP16(bb2 + stOff,   Bb + go);                                 \
        CP16(bb2 + stOff64, Bb + go + rstep);                         \
        CPCOMMIT();                                                   \
    } while (0)

    STAGE(0, 0);
    STAGE(1, 1);

    int buf = 0;
    for (int kt = 0; kt < nkt; kt++) {
        if (kt + 1 < nkt) CPWAIT1(); else CPWAIT0();
        __syncthreads();

        if (kt + 2 < nkt) {
            int nb = buf + 2; if (nb >= 3) nb -= 3;
            STAGE(kt + 2, nb);
        }

        uint32_t aBuf = sBase + (uint32_t)buf * BUFB;
        uint32_t bBuf = aBuf + OPB;
#pragma unroll
        for (int ks = 0; ks < 2; ks++) {
            int ko = ks * 16;
            unsigned bfr[4][2];
#pragma unroll
            for (int np = 0; np < 2; np++) {
                uint32_t ba = bBuf + (uint32_t)((nw + np * 16 + brow_l) * ASTRB
                                                + ko + bkof_l) * 2;
                LDSM4(bfr[np * 2][0], bfr[np * 2][1],
                      bfr[np * 2 + 1][0], bfr[np * 2 + 1][1], ba);
            }
#pragma unroll
            for (int mf = 0; mf < 4; mf++) {
                unsigned a0, a1, a2, a3;
                uint32_t aa = aBuf + (uint32_t)((mw + mf * 16 + arow_l) * ASTRB
                                                + ko + akof_l) * 2;
                LDSM4(a0, a1, a2, a3, aa);
#pragma unroll
                for (int nf = 0; nf < 4; nf++)
                    mma16816(acc + (mf * 4 + nf) * 4, a0, a1, a2, a3,
                             bfr[nf][0], bfr[nf][1]);
            }
        }
        if (++buf == 3) buf = 0;
    }
#undef STAGE

#pragma unroll
    for (int mf = 0; mf < 4; mf++) {
#pragma unroll
        for (int nf = 0; nf < 4; nf++) {
            float* c = acc + (mf * 4 + nf) * 4;
            int mg = m0 + mw + mf * 16 + lr;
            int ng = n0 + nw + nf * 8 + 2 * lc;
            float o0 = c[0] * alpha, o1 = c[1] * alpha;
            float o2 = c[2] * alpha, o3 = c[3] * alpha;
            if (BIAS_MODE == 1) {
                float b0 = bias[mg], b1 = bias[mg + 8];
                o0 += b0; o1 += b0; o2 += b1; o3 += b1;
            } else if (BIAS_MODE == 2) {
                float b0 = bias[ng], b1 = bias[ng + 1];
                o0 += b0; o1 += b1; o2 += b0; o3 += b1;
            }
            size_t i0 = (size_t)mg * N + ng;
            size_t i1 = (size_t)(mg + 8) * N + ng;
            if (RESID) {
                const float* Rb = resid + z * bC;
                o0 = (o0 + Rb[i0])     * outscale;
                o1 = (o1 + Rb[i0 + 1]) * outscale;
                o2 = (o2 + Rb[i1])     * outscale;
                o3 = (o3 + Rb[i1 + 1]) * outscale;
            }
            if (OUT_MODE == 1) {
                bf16* Cb = (bf16*)Cout + z * bC;
                *(uint32_t*)&Cb[i0] = pkbf(o0, o1);
                *(uint32_t*)&Cb[i1] = pkbf(o2, o3);
            } else if (OUT_MODE == 2) {
                __half* Cb = (__half*)Cout + z * bC;
                *(uint32_t*)&Cb[i0] = pkh(o0, o1);
                *(uint32_t*)&Cb[i1] = pkh(o2, o3);
            } else {
                float* Cb = (float*)Cout + z * bC;
                float2 p0 = {o0, o1}, p1 = {o2, o3};
                *(float2*)&Cb[i0] = p0;
                *(float2*)&Cb[i1] = p1;
            }
        }
    }
}

// ---------------------------------------------------------------------------
// Fused flash attention v5 — PV channel-split via P-in-smem.
//   S phase + softmax: row-split (v3 proven). P stored to smem tile
//   (round-14-proven conflict-free STS pattern). Per-row rescale factors
//   shared through ssc[128]; l via ones-MMA in the S-warp, shared at end.
//   PV: each warp owns 32 channels x all 128 rows — V B-fragments loaded
//   once per ks (2 LDSM) instead of 16 -> crossbar traffic cut ~35%.
// ---------------------------------------------------------------------------
#define QSTR 264
#define KSTR 264
#define VSTR 72
#define PSTR 136
#define Q_BYTES (128 * QSTR * 2)          // 67584
#define CHUNK_BYTES (256 * VSTR * 2)      // 36864
#define P_BYTES (128 * PSTR * 2)          // 34816
#define FSMEM (Q_BYTES + 3 * CHUNK_BYTES + P_BYTES + 512)   // 213504
#define ONES1 0x3C003C00u                 // half2(1.0, 1.0)

__global__ __launch_bounds__(256, 1) void attn_fused(
    const __half* __restrict__ qT, const __half* __restrict__ kT,
    const __half* __restrict__ vv, bf16* __restrict__ aoT)
{
    extern __shared__ char fsm[];
    uint32_t sq = (uint32_t)__cvta_generic_to_shared(fsm);
    uint32_t sring = sq + Q_BYTES;
    uint32_t sP = sring + 3 * CHUNK_BYTES;
    float* ssc = (float*)(fsm + Q_BYTES + 3 * CHUNK_BYTES + P_BYTES);
    const float a2f = 0.0625f * 1.4426950408889634f;   // alpha * log2(e)
    const __half2 a2h = __float2half2_rn(a2f);

    int t = threadIdx.x, wid = t >> 5, lane = t & 31;
    int lr = lane >> 2, lc = lane & 3;
    size_t z = blockIdx.y;
    int q0 = blockIdx.x * 128;

    const __half* qb = qT + z * CHB;
    const __half* kb = kT + z * CHB;
    const __half* vb = vv + z * CHB;

    int arow_l = (lane & 7) + ((lane >> 3) & 1) * 8;
    int akof_l = (lane >> 4) * 8;
    int brow_l = (lane & 7) + ((lane >> 4) & 1) * 8;
    int bkof_l = ((lane >> 3) & 1) * 8;

    // stage q tile
#pragma unroll
    for (int i = 0; i < 16; i++) {
        int idx = i * 256 + t;
        int row = idx >> 5, g = idx & 31;
        CP16(sq + (uint32_t)(row * QSTR + g * 8) * 2,
             qb + (size_t)(q0 + row) * NCH + g * 8);
    }
    CPCOMMIT();

    // PV accumulators: warp owns channels wid*32..+31, all 128 rows
    float outv[8][4][4];
#pragma unroll
    for (int rg = 0; rg < 8; rg++)
#pragma unroll
        for (int cg = 0; cg < 4; cg++) {
            outv[rg][cg][0] = 0.f; outv[rg][cg][1] = 0.f;
            outv[rg][cg][2] = 0.f; outv[rg][cg][3] = 0.f;
        }
    float lacc[4] = {0.f, 0.f, 0.f, 0.f};
    unsigned Sa2[16][2];
    float m_a0 = -1e30f, m_a1 = -1e30f;

    int s_idx = 0;
#define FSTAGE() do {                                                       \
        int ty_ = s_idx & 3, kti_ = s_idx >> 2;                             \
        uint32_t bs = sring + (uint32_t)(s_idx % 3) * CHUNK_BYTES;          \
        if (ty_ < 2) {                                                      \
            const __half* src = kb + (size_t)(kti_ * 128 + ty_ * 64) * NCH; \
            _Pragma("unroll")                                               \
            for (int i = 0; i < 8; i++) {                                   \
                int idx = i * 256 + t; int row = idx >> 5, g = idx & 31;    \
                CP16(bs + (uint32_t)(row * KSTR + g * 8) * 2,               \
                     src + (size_t)row * NCH + g * 8);                      \
            }                                                               \
        } else {                                                            \
            const __half* src = vb + kti_ * 128 + (ty_ - 2) * 64;           \
            _Pragma("unroll")                                               \
            for (int i = 0; i < 8; i++) {                                   \
                int idx = i * 256 + t; int row = idx >> 3, g = idx & 7;     \
                CP16(bs + (uint32_t)(row * VSTR + g * 8) * 2,               \
                     src + (size_t)row * NTOK + g * 8);                     \
            }                                                               \
        }                                                                   \
        CPCOMMIT();                                                         \
        s_idx++;                                                            \
    } while (0)

    FSTAGE();
    FSTAGE();

    int c_idx = 0;
    uint32_t bs_cur;
#define ADV() do {                                                          \
        if (c_idx < 127) CPWAIT1(); else CPWAIT0();                         \
        __syncthreads();                                                    \
        if (s_idx < 128) FSTAGE();                                          \
        bs_cur = sring + (uint32_t)(c_idx % 3) * CHUNK_BYTES;               \
        c_idx++;                                                            \
    } while (0)

    for (int kti = 0; kti < 32; kti++) {
        // ---- S = q . kT^T (fp16 accumulate, row-split) ----
#pragma unroll
        for (int h = 0; h < 2; h++) {
            ADV();
            if (h == 0) {
#pragma unroll
                for (int j = 0; j < 16; j++) { Sa2[j][0] = 0u; Sa2[j][1] = 0u; }
            }
#pragma unroll
            for (int ks = 0; ks < 16; ks++) {
                unsigned a0, a1, a2, a3;
                LDSM4(a0, a1, a2, a3,
                      sq + (uint32_t)((wid * 16 + arow_l) * QSTR
                                      + ks * 16 + akof_l) * 2);
#pragma unroll
                for (int ng = 0; ng < 4; ng++) {
                    unsigned b0, b1, b2, b3;
                    LDSM4(b0, b1, b2, b3,
                          bs_cur + (uint32_t)((ng * 16 + brow_l) * KSTR
                                              + ks * 16 + bkof_l) * 2);
                    int j = h * 8 + 2 * ng;
                    mma16816hh(Sa2[j],     a0, a1, a2, a3, b0, b1);
                    mma16816hh(Sa2[j + 1], a0, a1, a2, a3, b2, b3);
                }
            }
        }

        // ---- online softmax (row-split); share sc; P -> smem; l ones-MMA ----
        {
            __half2 x0 = *(__half2*)&Sa2[0][0];
            __half2 x1 = *(__half2*)&Sa2[0][1];
#pragma unroll
            for (int j = 1; j < 16; j++) {
                x0 = __hmax2(x0, *(__half2*)&Sa2[j][0]);
                x1 = __hmax2(x1, *(__half2*)&Sa2[j][1]);
            }
            unsigned u0 = *(unsigned*)&x0, u1 = *(unsigned*)&x1;
            u0 = __shfl_xor_sync(0xffffffffu, u0, 1);
            x0 = __hmax2(x0, *(__half2*)&u0);
            u1 = __shfl_xor_sync(0xffffffffu, u1, 1);
            x1 = __hmax2(x1, *(__half2*)&u1);
            u0 = *(unsigned*)&x0; u1 = *(unsigned*)&x1;
            u0 = __shfl_xor_sync(0xffffffffu, u0, 2);
            x0 = __hmax2(x0, *(__half2*)&u0);
            u1 = __shfl_xor_sync(0xffffffffu, u1, 2);
            x1 = __hmax2(x1, *(__half2*)&u1);
            float t0 = a2f * __half2float(__hmax(__low2half(x0), __high2half(x0)));
            float t1 = a2f * __half2float(__hmax(__low2half(x1), __high2half(x1)));
            float mn0 = fmaxf(m_a0, t0);
            float mn1 = fmaxf(m_a1, t1);
            float sc0 = exp2f(m_a0 - mn0);   // == 1.0 exactly when unchanged
            float sc1 = exp2f(m_a1 - mn1);
            m_a0 = mn0; m_a1 = mn1;
            lacc[0] *= sc0; lacc[1] *= sc0;
            lacc[2] *= sc1; lacc[3] *= sc1;
            if (lc == 0) {
                ssc[wid * 16 + lr]     = sc0;
                ssc[wid * 16 + lr + 8] = sc1;
            }

            __half2 nm0 = __float2half2_rn(-m_a0);
            __half2 nm1 = __float2half2_rn(-m_a1);
#pragma unroll
            for (int j = 0; j < 16; j++) {
                __half2 p0 = h2exp2(__hfma2(a2h, *(__half2*)&Sa2[j][0], nm0));
                __half2 p1 = h2exp2(__hfma2(a2h, *(__half2*)&Sa2[j][1], nm1));
                Sa2[j][0] = *(unsigned*)&p0;
                Sa2[j][1] = *(unsigned*)&p1;
                // store P to smem (conflict-free: bank = 4*lr + lc)
                int tok = ((j >> 3) * 64) + (((j >> 1) & 3) * 16)
                        + ((j & 1) * 8) + 2 * lc;
                STS32(sP + (uint32_t)((wid * 16 + lr) * PSTR + tok) * 2,
                      Sa2[j][0]);
                STS32(sP + (uint32_t)((wid * 16 + lr + 8) * PSTR + tok) * 2,
                      Sa2[j][1]);
            }
            // l for own rows: ones-column MMA over all 128 tokens
#pragma unroll
            for (int jj = 0; jj < 8; jj++)
                mma16816h(lacc, Sa2[2 * jj][0], Sa2[2 * jj][1],
                          Sa2[2 * jj + 1][0], Sa2[2 * jj + 1][1], ONES1, ONES1);
        }

        // ---- PV phase (channel-split): warp = 32 channels x all rows ----
#pragma unroll
        for (int h = 0; h < 2; h++) {
            ADV();   // barrier makes sP + ssc visible
            if (h == 0) {
                // rescale all accumulated rows by their sc
#pragma unroll
                for (int rg = 0; rg < 8; rg++) {
                    float s0 = ssc[rg * 16 + lr];
                    float s1 = ssc[rg * 16 + lr + 8];
#pragma unroll
                    for (int cg = 0; cg < 4; cg++) {
                        outv[rg][cg][0] *= s0; outv[rg][cg][1] *= s0;
                        outv[rg][cg][2] *= s1; outv[rg][cg][3] *= s1;
                    }
                }
            }
#pragma unroll
            for (int ks = 0; ks < 4; ks++) {
                unsigned b0, b1, b2, b3, b4, b5, b6, b7;
                LDSM4(b0, b1, b2, b3,
                      bs_cur + (uint32_t)((wid * 32 + brow_l) * VSTR
                                          + ks * 16 + bkof_l) * 2);
                LDSM4(b4, b5, b6, b7,
                      bs_cur + (uint32_t)((wid * 32 + 16 + brow_l) * VSTR
                                          + ks * 16 + bkof_l) * 2);
#pragma unroll
                for (int rg = 0; rg < 8; rg++) {
                    unsigned a0, a1, a2, a3;
                    LDSM4(a0, a1, a2, a3,
                          sP + (uint32_t)((rg * 16 + arow_l) * PSTR
                                          + h * 64 + ks * 16 + akof_l) * 2);
                    mma16816h(outv[rg][0], a0, a1, a2, a3, b0, b1);
                    mma16816h(outv[rg][1], a0, a1, a2, a3, b2, b3);
                    mma16816h(outv[rg][2], a0, a1, a2, a3, b4, b5);
                    mma16816h(outv[rg][3], a0, a1, a2, a3, b6, b7);
                }
            }
        }
    }
#undef ADV
#undef FSTAGE

    // ---- share l, then normalize + write bf16 aoT ----
    if (lc == 0) {
        ssc[wid * 16 + lr]     = lacc[0];
        ssc[wid * 16 + lr + 8] = lacc[2];
    }
    __syncthreads();

    bf16* ao = aoT + z * CHB;
#pragma unroll
    for (int rg = 0; rg < 8; rg++) {
        int r = rg * 16 + lr;
        float i0 = 1.f / ssc[r];
        float i1 = 1.f / ssc[r + 8];
#pragma unroll
        for (int cg = 0; cg < 4; cg++) {
            int col = wid * 32 + cg * 8 + 2 * lc;
            *(uint32_t*)&ao[(size_t)(q0 + r) * NCH + col] =
                pkbf(outv[rg][cg][0] * i0, outv[rg][cg][1] * i0);
            *(uint32_t*)&ao[(size_t)(q0 + r + 8) * NCH + col] =
                pkbf(outv[rg][cg][2] * i1, outv[rg][cg][3] * i1);
        }
    }
}

// ---------------------------------------------------------------------------
// kernel_launch — scratch via cudaGetSymbolAddress (true device addresses).
// ---------------------------------------------------------------------------
extern "C" void kernel_launch(void* const* d_in, const int* in_sizes, int n_in,
                              void* d_out, int out_size)
{
    const float* x   = (const float*)d_in[0];
    const float* gns = (const float*)d_in[1];
    const float* gnb = (const float*)d_in[2];
    const float* wq  = (const float*)d_in[3];
    const float* bq  = (const float*)d_in[4];
    const float* wk  = (const float*)d_in[5];
    const float* bk  = (const float*)d_in[6];
    const float* wv  = (const float*)d_in[7];
    const float* bv  = (const float*)d_in[8];
    const float* wo  = (const float*)d_in[9];
    const float* bo  = (const float*)d_in[10];
    float* out = (float*)d_out;

    void *p_stat, *p_hnT, *p_qT, *p_kT, *p_v, *p_aoT, *p_wb;
    cudaGetSymbolAddress(&p_stat, g_stat);
    cudaGetSymbolAddress(&p_hnT, g_hnT);
    cudaGetSymbolAddress(&p_qT,  g_qT);
    cudaGetSymbolAddress(&p_kT,  g_kT);
    cudaGetSymbolAddress(&p_v,   g_v);
    cudaGetSymbolAddress(&p_aoT, g_aoT);
    cudaGetSymbolAddress(&p_wb,  g_wb);
    float*  stat = (float*)p_stat;
    bf16*   hnT = (bf16*)p_hnT;
    __half* qT  = (__half*)p_qT;
    __half* kT  = (__half*)p_kT;
    __half* v   = (__half*)p_v;
    bf16*   aoT = (bf16*)p_aoT;
    bf16*   wb  = (bf16*)p_wb;

    cudaFuncSetAttribute(hgemm<2, 2, 0>, cudaFuncAttributeMaxDynamicSharedMemorySize, SMEM_DYN);
    cudaFuncSetAttribute(hgemm<2, 1, 0>, cudaFuncAttributeMaxDynamicSharedMemorySize, SMEM_DYN);
    cudaFuncSetAttribute(hgemm<0, 1, 1>, cudaFuncAttributeMaxDynamicSharedMemorySize, SMEM_DYN);
    cudaFuncSetAttribute(attn_fused, cudaFuncAttributeMaxDynamicSharedMemorySize, FSMEM);

    // 0) bf16 weights + GroupNorm stats + normalize-in-transpose
    prep_kernel<<<256, 256>>>(wq, wk, wv, wo, wb);
    gn_stats_kernel<<<NB * 32, 256>>>(x, stat);
    transpose_norm_kernel<<<dim3(NTOK / 32, NCH / 32, NB), 256>>>(
        x, stat, gns, gnb, hnT);

    // 1) qT[tok][ch] = hnT . wq^T + bq (fp16 out); kT likewise
    hgemm<2, 2, 0><<<dim3(2, 32, NB), 256, SMEM_DYN>>>(
        hnT, wb, qT, bq, nullptr, 1.f, 1.f,
        NTOK, NCH, NCH, CHB, 0, CHB);
    hgemm<2, 2, 0><<<dim3(2, 32, NB), 256, SMEM_DYN>>>(
        hnT, wb + 65536, kT, bk, nullptr, 1.f, 1.f,
        NTOK, NCH, NCH, CHB, 0, CHB);
    // v[ch][tok] = wv . hnT^T + bv (fp16 out)
    hgemm<2, 1, 0><<<dim3(32, 2, NB), 256, SMEM_DYN>>>(
        wb + 131072, hnT, v, bv, nullptr, 1.f, 1.f,
        NCH, NTOK, NCH, 0, CHB, CHB);

    // 2) fused attention v5 (PV channel-split)
    attn_fused<<<dim3(32, NB), 256, FSMEM>>>(qT, kT, v, aoT);

    // 3) out[ch][tok] = (wo . aoT^T + bo + x) / sqrt(2)
    hgemm<0, 1, 1><<<dim3(32, 2, NB), 256, SMEM_DYN>>>(
        wb + 196608, aoT, out, bo, x, 1.f, 0.70710678118654752f,
        NCH, NTOK, NCH, 0, CHB, CHB);
}

// round 17
// speedup vs baseline: 1.0173x; 1.0173x over previous
#include <cuda_runtime.h>
#include <cuda_bf16.h>
#include <cuda_fp16.h>
#include <cstdint>
#include <cstddef>

// Problem constants
#define NB    8
#define NCH   256
#define NTOK  4096
#define CHB   ((size_t)NCH * NTOK)
#define QKS   512                      // combined qk row stride

typedef __nv_bfloat16 bf16;

// Static scratch — accessed ONLY via cudaGetSymbolAddress-resolved pointers.
__device__ __align__(256) float  g_stat[NB * 32 * 2];   // groupnorm mean/rstd
__device__ __align__(256) float  g_bqk[QKS];            // [bq ; bk]
__device__ __align__(256) bf16   g_hnT[NB * CHB];       // [tok][ch] bf16
__device__ __align__(256) __half g_qkT[NB * (size_t)NTOK * QKS]; // [tok][512] fp16
__device__ __align__(256) __half g_v  [NB * CHB];       // [ch][tok] fp16
__device__ __align__(256) bf16   g_aoT[NB * CHB];       // [tok][ch] bf16
__device__ __align__(256) bf16   g_wb [4 * NCH * NCH];  // bf16 weights q,k,v,o

// ---------------------------------------------------------------------------
// common PTX helpers
// ---------------------------------------------------------------------------
__device__ __forceinline__ void mma16816(float* c, unsigned a0, unsigned a1,
                                         unsigned a2, unsigned a3,
                                         unsigned b0, unsigned b1)
{
    asm volatile(
        "mma.sync.aligned.m16n8k16.row.col.f32.bf16.bf16.f32 "
        "{%0,%1,%2,%3},{%4,%5,%6,%7},{%8,%9},{%0,%1,%2,%3};"
        : "+f"(c[0]), "+f"(c[1]), "+f"(c[2]), "+f"(c[3])
        : "r"(a0), "r"(a1), "r"(a2), "r"(a3), "r"(b0), "r"(b1));
}

// fp16 operands, fp32 accumulate (PV + l)
__device__ __forceinline__ void mma16816h(float* c, unsigned a0, unsigned a1,
                                          unsigned a2, unsigned a3,
                                          unsigned b0, unsigned b1)
{
    asm volatile(
        "mma.sync.aligned.m16n8k16.row.col.f32.f16.f16.f32 "
        "{%0,%1,%2,%3},{%4,%5,%6,%7},{%8,%9},{%0,%1,%2,%3};"
        : "+f"(c[0]), "+f"(c[1]), "+f"(c[2]), "+f"(c[3])
        : "r"(a0), "r"(a1), "r"(a2), "r"(a3), "r"(b0), "r"(b1));
}

// fp16 operands, fp16 accumulate (S logits)
__device__ __forceinline__ void mma16816hh(unsigned* c, unsigned a0, unsigned a1,
                                           unsigned a2, unsigned a3,
                                           unsigned b0, unsigned b1)
{
    asm volatile(
        "mma.sync.aligned.m16n8k16.row.col.f16.f16.f16.f16 "
        "{%0,%1},{%2,%3,%4,%5},{%6,%7},{%0,%1};"
        : "+r"(c[0]), "+r"(c[1])
        : "r"(a0), "r"(a1), "r"(a2), "r"(a3), "r"(b0), "r"(b1));
}

#define LDSM4(r0, r1, r2, r3, addr) \
    asm volatile("ldmatrix.sync.aligned.m8n8.x4.shared.b16 {%0,%1,%2,%3}, [%4];" \
                 : "=r"(r0), "=r"(r1), "=r"(r2), "=r"(r3) : "r"(addr))

#define CP16(dst, src) \
    asm volatile("cp.async.cg.shared.global [%0], [%1], 16;" :: "r"(dst), "l"(src))
#define CPCOMMIT() asm volatile("cp.async.commit_group;" ::: "memory")
#define CPWAIT1()  asm volatile("cp.async.wait_group 1;" ::: "memory")
#define CPWAIT0()  asm volatile("cp.async.wait_group 0;" ::: "memory")

__device__ __forceinline__ unsigned pkbf(float x, float y) {
    __nv_bfloat162 h = __floats2bfloat162_rn(x, y);
    return *(unsigned*)&h;
}
__device__ __forceinline__ unsigned pkh(float x, float y) {
    __half2 h = __floats2half2_rn(x, y);
    return *(unsigned*)&h;
}

// ---------------------------------------------------------------------------
// prep + gn_stats merged: blocks 0-255 convert weights (+combined qk bias);
// blocks 256-511 compute groupnorm stats (bg = bx - 256).
// ---------------------------------------------------------------------------
__global__ __launch_bounds__(256) void prep_gn_kernel(
    const float* __restrict__ wq, const float* __restrict__ wk,
    const float* __restrict__ wv, const float* __restrict__ wo,
    const float* __restrict__ bq, const float* __restrict__ bk,
    bf16* __restrict__ wb, float* __restrict__ bqk,
    const float* __restrict__ x, float* __restrict__ stat)
{
    int bx = blockIdx.x, t = threadIdx.x;
    if (bx < 256) {
        int i = bx * 256 + t;
        wb[i]          = __float2bfloat16(wq[i]);
        wb[ 65536 + i] = __float2bfloat16(wk[i]);
        wb[131072 + i] = __float2bfloat16(wv[i]);
        wb[196608 + i] = __float2bfloat16(wo[i]);
        if (bx == 0) bqk[t] = bq[t];
        if (bx == 1) bqk[256 + t] = bk[t];
        return;
    }
    int bg = bx - 256;             // b*32 + g
    size_t base = (size_t)bg * 8 * NTOK;
    const float4* px = (const float4*)(x + base);

    float s = 0.f, ss = 0.f;
#pragma unroll
    for (int r = 0; r < 32; r++) {
        float4 f = px[r * 256 + t];
        s  += f.x + f.y + f.z + f.w;
        ss += f.x * f.x + f.y * f.y + f.z * f.z + f.w * f.w;
    }
#pragma unroll
    for (int o = 16; o; o >>= 1) {
        s  += __shfl_xor_sync(0xffffffffu, s, o);
        ss += __shfl_xor_sync(0xffffffffu, ss, o);
    }
    __shared__ float rs[8], rss[8];
    if ((t & 31) == 0) { rs[t >> 5] = s; rss[t >> 5] = ss; }
    __syncthreads();
    if (t == 0) {
        float S = 0.f, SS = 0.f;
#pragma unroll
        for (int i = 0; i < 8; i++) { S += rs[i]; SS += rss[i]; }
        float m = S * (1.f / 32768.f);
        float var = SS * (1.f / 32768.f) - m * m;
        stat[bg * 2]     = m;
        stat[bg * 2 + 1] = rsqrtf(var + 1e-6f);
    }
}

// ---------------------------------------------------------------------------
// Transpose + normalize: x [256][4096] fp32 -> hnT [4096][256] bf16
// ---------------------------------------------------------------------------
__global__ __launch_bounds__(256) void transpose_norm_kernel(
    const float* __restrict__ x, const float* __restrict__ stat,
    const float* __restrict__ sc, const float* __restrict__ bi,
    bf16* __restrict__ out)
{
    __shared__ float tile[32][33];
    size_t z = blockIdx.z;
    const float* ip = x + z * CHB;
    bf16* op = out + z * CHB;
    int n0 = blockIdx.x * 32, c0 = blockIdx.y * 32;
    int tx = threadIdx.x & 31, ty = threadIdx.x >> 5;
#pragma unroll
    for (int j = 0; j < 32; j += 8) {
        int c = c0 + ty + j;
        float mean = stat[(z * 32 + (c >> 3)) * 2];
        float rstd = stat[(z * 32 + (c >> 3)) * 2 + 1];
        float a = sc[c] * rstd;
        float bb = bi[c] - mean * a;
        tile[ty + j][tx] = ip[(size_t)c * NTOK + n0 + tx] * a + bb;
    }
    __syncthreads();
#pragma unroll
    for (int j = 0; j < 32; j += 8)
        op[(size_t)(n0 + ty + j) * NCH + c0 + tx] = __float2bfloat16(tile[tx][ty + j]);
}

// ---------------------------------------------------------------------------
// hgemm: warp-MMA bf16 GEMM, 3-stage cp.async pipeline (round-9 proven).
// OUT_MODE: 0 fp32, 1 bf16, 2 fp16.
// ---------------------------------------------------------------------------
#define ASTRB 40
#define OPB   (128 * ASTRB * 2)
#define BUFB  (2 * OPB)
#define SMEM_DYN (3 * BUFB)

template<int OUT_MODE, int BIAS_MODE, int RESID>
__global__ __launch_bounds__(256, 2) void hgemm(
    const bf16* __restrict__ A, const bf16* __restrict__ B,
    void* __restrict__ Cout, const float* __restrict__ bias,
    const float* __restrict__ resid, float alpha, float outscale,
    int M, int N, int K, size_t bA, size_t bB, size_t bC)
{
    extern __shared__ char dynsm[];
    uint32_t sBase = (uint32_t)__cvta_generic_to_shared(dynsm);

    int t = threadIdx.x;
    int m0 = blockIdx.y * 128, n0 = blockIdx.x * 128;
    size_t z = blockIdx.z;

    int wid = t >> 5, lane = t & 31;
    int mw = (wid & 1) * 64, nw = (wid >> 1) * 32;
    int lr = lane >> 2, lc = lane & 3;

    float acc[64];
#pragma unroll
    for (int i = 0; i < 64; i++) acc[i] = 0.f;

    int rowa = t >> 2, gcol = t & 3;
    const bf16* Ab = A + z * bA + (size_t)(m0 + rowa) * K + gcol * 8;
    const bf16* Bb = B + z * bB + (size_t)(n0 + rowa) * K + gcol * 8;
    size_t rstep = (size_t)64 * K;

    uint32_t stOff   = (uint32_t)(rowa * ASTRB + gcol * 8) * 2;
    uint32_t stOff64 = stOff + (uint32_t)(64 * ASTRB) * 2;

    int arow_l = (lane & 7) + ((lane >> 3) & 1) * 8;
    int akof_l = (lane >> 4) * 8;
    int brow_l = (lane & 7) + ((lane >> 4) & 1) * 8;
    int bkof_l = ((lane >> 3) & 1) * 8;

    int nkt = K / 32;

#define STAGE(chunk, buf) do {                                        \
        size_t go = (size_t)(chunk) * 32;                             \
        uint32_t ab = sBase + (uint32_t)(buf) * BUFB;                 \
        uint32_t bb2 = ab + OPB;                                      \
        CP16(ab + stOff,    Ab + go);                                 \
        CP16(ab + stOff64,  Ab + go + rstep);                         \
        CP16(bb2 + stOff,   Bb + go);                                 \
        CP16(bb2 + stOff64, Bb + go + rstep);                         \
        CPCOMMIT();                                                   \
    } while (0)

    STAGE(0, 0);
    STAGE(1, 1);

    int buf = 0;
    for (int kt = 0; kt < nkt; kt++) {
        if (kt + 1 < nkt) CPWAIT1(); else CPWAIT0();
        __syncthreads();

        if (kt + 2 < nkt) {
            int nb = buf + 2; if (nb >= 3) nb -= 3;
            STAGE(kt + 2, nb);
        }

        uint32_t aBuf = sBase + (uint32_t)buf * BUFB;
        uint32_t bBuf = aBuf + OPB;
#pragma unroll
        for (int ks = 0; ks < 2; ks++) {
            int ko = ks * 16;
            unsigned bfr[4][2];
#pragma unroll
            for (int np = 0; np < 2; np++) {
                uint32_t ba = bBuf + (uint32_t)((nw + np * 16 + brow_l) * ASTRB
                                                + ko + bkof_l) * 2;
                LDSM4(bfr[np * 2][0], bfr[np * 2][1],
                      bfr[np * 2 + 1][0], bfr[np * 2 + 1][1], ba);
            }
#pragma unroll
            for (int mf = 0; mf < 4; mf++) {
                unsigned a0, a1, a2, a3;
                uint32_t aa = aBuf + (uint32_t)((mw + mf * 16 + arow_l) * ASTRB
                                                + ko + akof_l) * 2;
                LDSM4(a0, a1, a2, a3, aa);
#pragma unroll
                for (int nf = 0; nf < 4; nf++)
                    mma16816(acc + (mf * 4 + nf) * 4, a0, a1, a2, a3,
                             bfr[nf][0], bfr[nf][1]);
            }
        }
        if (++buf == 3) buf = 0;
    }
#undef STAGE

#pragma unroll
    for (int mf = 0; mf < 4; mf++) {
#pragma unroll
        for (int nf = 0; nf < 4; nf++) {
            float* c = acc + (mf * 4 + nf) * 4;
            int mg = m0 + mw + mf * 16 + lr;
            int ng = n0 + nw + nf * 8 + 2 * lc;
            float o0 = c[0] * alpha, o1 = c[1] * alpha;
            float o2 = c[2] * alpha, o3 = c[3] * alpha;
            if (BIAS_MODE == 1) {
                float b0 = bias[mg], b1 = bias[mg + 8];
                o0 += b0; o1 += b0; o2 += b1; o3 += b1;
            } else if (BIAS_MODE == 2) {
                float b0 = bias[ng], b1 = bias[ng + 1];
                o0 += b0; o1 += b1; o2 += b0; o3 += b1;
            }
            size_t i0 = (size_t)mg * N + ng;
            size_t i1 = (size_t)(mg + 8) * N + ng;
            if (RESID) {
                const float* Rb = resid + z * bC;
                o0 = (o0 + Rb[i0])     * outscale;
                o1 = (o1 + Rb[i0 + 1]) * outscale;
                o2 = (o2 + Rb[i1])     * outscale;
                o3 = (o3 + Rb[i1 + 1]) * outscale;
            }
            if (OUT_MODE == 1) {
                bf16* Cb = (bf16*)Cout + z * bC;
                *(uint32_t*)&Cb[i0] = pkbf(o0, o1);
                *(uint32_t*)&Cb[i1] = pkbf(o2, o3);
            } else if (OUT_MODE == 2) {
                __half* Cb = (__half*)Cout + z * bC;
                *(uint32_t*)&Cb[i0] = pkh(o0, o1);
                *(uint32_t*)&Cb[i1] = pkh(o2, o3);
            } else {
                float* Cb = (float*)Cout + z * bC;
                float2 p0 = {o0, o1}, p1 = {o2, o3};
                *(float2*)&Cb[i0] = p0;
                *(float2*)&Cb[i1] = p1;
            }
        }
    }
}

// ---------------------------------------------------------------------------
// Fused flash attention v3 (round-12/15 proven), reading the combined qkT
// buffer: q = row*QKS + [0,256), k = row*QKS + 256 + [0,256).
// ---------------------------------------------------------------------------
#define QSTR 264
#define KSTR 264
#define VSTR 72
#define Q_BYTES (128 * QSTR * 2)          // 67584
#define CHUNK_BYTES (256 * VSTR * 2)      // 36864
#define FSMEM (Q_BYTES + 3 * CHUNK_BYTES) // 178176
#define ONES1 0x3C003C00u                 // half2(1.0, 1.0)

__global__ __launch_bounds__(256, 1) void attn_fused(
    const __half* __restrict__ qkT, const __half* __restrict__ vv,
    bf16* __restrict__ aoT)
{
    extern __shared__ char fsm[];
    uint32_t sq = (uint32_t)__cvta_generic_to_shared(fsm);
    uint32_t sring = sq + Q_BYTES;
    const float a2f = 0.0625f * 1.4426950408889634f;   // alpha * log2(e)
    const __half2 a2h = __float2half2_rn(a2f);

    int t = threadIdx.x, wid = t >> 5, lane = t & 31;
    int lr = lane >> 2, lc = lane & 3;
    size_t z = blockIdx.y;
    int q0 = blockIdx.x * 128;

    const __half* qb = qkT + z * ((size_t)NTOK * QKS);
    const __half* kb = qb + 256;
    const __half* vb = vv + z * CHB;

    int arow_l = (lane & 7) + ((lane >> 3) & 1) * 8;
    int akof_l = (lane >> 4) * 8;
    int brow_l = (lane & 7) + ((lane >> 4) & 1) * 8;
    int bkof_l = ((lane >> 3) & 1) * 8;

    // stage q tile (rows stride QKS in global)
#pragma unroll
    for (int i = 0; i < 16; i++) {
        int idx = i * 256 + t;
        int row = idx >> 5, g = idx & 31;
        CP16(sq + (uint32_t)(row * QSTR + g * 8) * 2,
             qb + (size_t)(q0 + row) * QKS + g * 8);
    }
    CPCOMMIT();

    float out[32][4];
#pragma unroll
    for (int g = 0; g < 32; g++) {
        out[g][0] = 0.f; out[g][1] = 0.f; out[g][2] = 0.f; out[g][3] = 0.f;
    }
    float lacc[4] = {0.f, 0.f, 0.f, 0.f};
    unsigned Sa2[16][2];
    float m_a0 = -1e30f, m_a1 = -1e30f;

    int s_idx = 0;
#define FSTAGE() do {                                                       \
        int ty_ = s_idx & 3, kti_ = s_idx >> 2;                             \
        uint32_t bs = sring + (uint32_t)(s_idx % 3) * CHUNK_BYTES;          \
        if (ty_ < 2) {                                                      \
            const __half* src = kb + (size_t)(kti_ * 128 + ty_ * 64) * QKS; \
            _Pragma("unroll")                                               \
            for (int i = 0; i < 8; i++) {                                   \
                int idx = i * 256 + t; int row = idx >> 5, g = idx & 31;    \
                CP16(bs + (uint32_t)(row * KSTR + g * 8) * 2,               \
                     src + (size_t)row * QKS + g * 8);                      \
            }                                                               \
        } else {                                                            \
            const __half* src = vb + kti_ * 128 + (ty_ - 2) * 64;           \
            _Pragma("unroll")                                               \
            for (int i = 0; i < 8; i++) {                                   \
                int idx = i * 256 + t; int row = idx >> 3, g = idx & 7;     \
                CP16(bs + (uint32_t)(row * VSTR + g * 8) * 2,               \
                     src + (size_t)row * NTOK + g * 8);                     \
            }                                                               \
        }                                                                   \
        CPCOMMIT();                                                         \
        s_idx++;                                                            \
    } while (0)

    FSTAGE();
    FSTAGE();

    int c_idx = 0;
    uint32_t bs_cur;
#define ADV() do {                                                          \
        if (c_idx < 127) CPWAIT1(); else CPWAIT0();                         \
        __syncthreads();                                                    \
        if (s_idx < 128) FSTAGE();                                          \
        bs_cur = sring + (uint32_t)(c_idx % 3) * CHUNK_BYTES;               \
        c_idx++;                                                            \
    } while (0)

    for (int kti = 0; kti < 32; kti++) {
        // ---- S = q . kT^T (fp16 accumulate) : two 64-token halves ----
#pragma unroll
        for (int h = 0; h < 2; h++) {
            ADV();
            if (h == 0) {
#pragma unroll
                for (int j = 0; j < 16; j++) { Sa2[j][0] = 0u; Sa2[j][1] = 0u; }
            }
#pragma unroll
            for (int ks = 0; ks < 16; ks++) {
                unsigned a0, a1, a2, a3;
                LDSM4(a0, a1, a2, a3,
                      sq + (uint32_t)((wid * 16 + arow_l) * QSTR
                                      + ks * 16 + akof_l) * 2);
#pragma unroll
                for (int ng = 0; ng < 4; ng++) {
                    unsigned b0, b1, b2, b3;
                    LDSM4(b0, b1, b2, b3,
                          bs_cur + (uint32_t)((ng * 16 + brow_l) * KSTR
                                              + ks * 16 + bkof_l) * 2);
                    int j = h * 8 + 2 * ng;
                    mma16816hh(Sa2[j],     a0, a1, a2, a3, b0, b1);
                    mma16816hh(Sa2[j + 1], a0, a1, a2, a3, b2, b3);
                }
            }
        }

        // ---- online softmax (exp2 domain, half2) ----
        {
            __half2 x0 = *(__half2*)&Sa2[0][0];
            __half2 x1 = *(__half2*)&Sa2[0][1];
#pragma unroll
            for (int j = 1; j < 16; j++) {
                x0 = __hmax2(x0, *(__half2*)&Sa2[j][0]);
                x1 = __hmax2(x1, *(__half2*)&Sa2[j][1]);
            }
            unsigned u0 = *(unsigned*)&x0, u1 = *(unsigned*)&x1;
            u0 = __shfl_xor_sync(0xffffffffu, u0, 1);
            x0 = __hmax2(x0, *(__half2*)&u0);
            u1 = __shfl_xor_sync(0xffffffffu, u1, 1);
            x1 = __hmax2(x1, *(__half2*)&u1);
            u0 = *(unsigned*)&x0; u1 = *(unsigned*)&x1;
            u0 = __shfl_xor_sync(0xffffffffu, u0, 2);
            x0 = __hmax2(x0, *(__half2*)&u0);
            u1 = __shfl_xor_sync(0xffffffffu, u1, 2);
            x1 = __hmax2(x1, *(__half2*)&u1);
            float t0 = a2f * __half2float(__hmax(__low2half(x0), __high2half(x0)));
            float t1 = a2f * __half2float(__hmax(__low2half(x1), __high2half(x1)));
            float mn0 = fmaxf(m_a0, t0);
            float mn1 = fmaxf(m_a1, t1);

            bool need = (mn0 > m_a0) || (mn1 > m_a1);
            if (__any_sync(0xffffffffu, need)) {
                float sc0 = exp2f(m_a0 - mn0);
                float sc1 = exp2f(m_a1 - mn1);
#pragma unroll
                for (int g = 0; g < 32; g++) {
                    out[g][0] *= sc0; out[g][1] *= sc0;
                    out[g][2] *= sc1; out[g][3] *= sc1;
                }
                lacc[0] *= sc0; lacc[1] *= sc0;
                lacc[2] *= sc1; lacc[3] *= sc1;
                m_a0 = mn0; m_a1 = mn1;
            }

            __half2 nm0 = __float2half2_rn(-m_a0);
            __half2 nm1 = __float2half2_rn(-m_a1);
#pragma unroll
            for (int j = 0; j < 16; j++) {
                __half2 p0 = h2exp2(__hfma2(a2h, *(__half2*)&Sa2[j][0], nm0));
                __half2 p1 = h2exp2(__hfma2(a2h, *(__half2*)&Sa2[j][1], nm1));
                Sa2[j][0] = *(unsigned*)&p0;
                Sa2[j][1] = *(unsigned*)&p1;
            }
        }

        // ---- out += P . v^T (fp32 accumulate); l via ones-column ----
#pragma unroll
        for (int h = 0; h < 2; h++) {
            ADV();
#pragma unroll
            for (int ks = 0; ks < 4; ks++) {
                int j0 = (h * 4 + ks) * 2;
                unsigned a0 = Sa2[j0][0];
                unsigned a1 = Sa2[j0][1];
                unsigned a2 = Sa2[j0 + 1][0];
                unsigned a3 = Sa2[j0 + 1][1];
                mma16816h(lacc, a0, a1, a2, a3, ONES1, ONES1);
#pragma unroll
                for (int ng = 0; ng < 16; ng++) {
                    unsigned b0, b1, b2, b3;
                    LDSM4(b0, b1, b2, b3,
                          bs_cur + (uint32_t)((ng * 16 + brow_l) * VSTR
                                              + ks * 16 + bkof_l) * 2);
                    mma16816h(out[2 * ng],     a0, a1, a2, a3, b0, b1);
                    mma16816h(out[2 * ng + 1], a0, a1, a2, a3, b2, b3);
                }
            }
        }
    }
#undef ADV
#undef FSTAGE

    // ---- epilogue: normalize by l (exact row sums from ones-MMA) ----
    float i0 = 1.f / lacc[0];
    float i1 = 1.f / lacc[2];

    bf16* ao = aoT + z * CHB;
    int r0 = q0 + wid * 16 + lr;
#pragma unroll
    for (int g = 0; g < 32; g++) {
        int col = g * 8 + 2 * lc;
        *(uint32_t*)&ao[(size_t)r0 * NCH + col]       = pkbf(out[g][0] * i0, out[g][1] * i0);
        *(uint32_t*)&ao[(size_t)(r0 + 8) * NCH + col] = pkbf(out[g][2] * i1, out[g][3] * i1);
    }
}

// ---------------------------------------------------------------------------
// kernel_launch — scratch via cudaGetSymbolAddress (true device addresses).
// ---------------------------------------------------------------------------
extern "C" void kernel_launch(void* const* d_in, const int* in_sizes, int n_in,
                              void* d_out, int out_size)
{
    const float* x   = (const float*)d_in[0];
    const float* gns = (const float*)d_in[1];
    const float* gnb = (const float*)d_in[2];
    const float* wq  = (const float*)d_in[3];
    const float* bq  = (const float*)d_in[4];
    const float* wk  = (const float*)d_in[5];
    const float* bk  = (const float*)d_in[6];
    const float* wv  = (const float*)d_in[7];
    const float* bv  = (const float*)d_in[8];
    const float* wo  = (const float*)d_in[9];
    const float* bo  = (const float*)d_in[10];
    float* out = (float*)d_out;

    void *p_stat, *p_bqk, *p_hnT, *p_qkT, *p_v, *p_aoT, *p_wb;
    cudaGetSymbolAddress(&p_stat, g_stat);
    cudaGetSymbolAddress(&p_bqk,  g_bqk);
    cudaGetSymbolAddress(&p_hnT,  g_hnT);
    cudaGetSymbolAddress(&p_qkT,  g_qkT);
    cudaGetSymbolAddress(&p_v,    g_v);
    cudaGetSymbolAddress(&p_aoT,  g_aoT);
    cudaGetSymbolAddress(&p_wb,   g_wb);
    float*  stat = (float*)p_stat;
    float*  bqk  = (float*)p_bqk;
    bf16*   hnT  = (bf16*)p_hnT;
    __half* qkT  = (__half*)p_qkT;
    __half* v    = (__half*)p_v;
    bf16*   aoT  = (bf16*)p_aoT;
    bf16*   wb   = (bf16*)p_wb;

    cudaFuncSetAttribute(hgemm<2, 2, 0>, cudaFuncAttributeMaxDynamicSharedMemorySize, SMEM_DYN);
    cudaFuncSetAttribute(hgemm<2, 1, 0>, cudaFuncAttributeMaxDynamicSharedMemorySize, SMEM_DYN);
    cudaFuncSetAttribute(hgemm<0, 1, 1>, cudaFuncAttributeMaxDynamicSharedMemorySize, SMEM_DYN);
    cudaFuncSetAttribute(attn_fused, cudaFuncAttributeMaxDynamicSharedMemorySize, FSMEM);

    // 0) weights->bf16 + combined qk bias + GN stats (one launch), then
    //    normalize-in-transpose
    prep_gn_kernel<<<512, 256>>>(wq, wk, wv, wo, bq, bk, wb, bqk, x, stat);
    transpose_norm_kernel<<<dim3(NTOK / 32, NCH / 32, NB), 256>>>(
        x, stat, gns, gnb, hnT);

    // 1) combined qk projection: qkT[tok][0:512] = hnT . [wq;wk]^T + [bq;bk]
    hgemm<2, 2, 0><<<dim3(4, 32, NB), 256, SMEM_DYN>>>(
        hnT, wb, qkT, bqk, nullptr, 1.f, 1.f,
        NTOK, QKS, NCH, CHB, 0, (size_t)NTOK * QKS);
    // v[ch][tok] = wv . hnT^T + bv (fp16 out)
    hgemm<2, 1, 0><<<dim3(32, 2, NB), 256, SMEM_DYN>>>(
        wb + 131072, hnT, v, bv, nullptr, 1.f, 1.f,
        NCH, NTOK, NCH, 0, CHB, CHB);

    // 2) fused attention (proven v3) on combined qkT
    attn_fused<<<dim3(32, NB), 256, FSMEM>>>(qkT, v, aoT);

    // 3) out[ch][tok] = (wo . aoT^T + bo + x) / sqrt(2)
    hgemm<0, 1, 1><<<dim3(32, 2, NB), 256, SMEM_DYN>>>(
        wb + 196608, aoT, out, bo, x, 1.f, 0.70710678118654752f,
        NCH, NTOK, NCH, 0, CHB, CHB);
}